// round 1
// baseline (speedup 1.0000x reference)
#include <cuda_runtime.h>
#include <cstdint>

// ---------------------------------------------------------------------------
// DisenGCN on GB300: PCA GEMM + 6 x (linear + capsule routing) -> concat out
// N=20000 nodes, M=16 neighbors, FEAT=500, d=16, CAPS={8,7,6,5,4,3}, 5 iters
// ---------------------------------------------------------------------------

#define NNODES 20000
#define MNBR   16
#define FEAT   500
#define DDIM   16
#define OUTW   656

// scratch (device globals; no allocation allowed)
__device__ float g_lin[NNODES * 128];    // linear output (pre-normalize)
__device__ float g_xnorm[NNODES * 128];  // per-capsule L2-normalized x

// ---------------------------------------------------------------------------
// GEMM: C[M,N] = (relu?)(A[M,K] @ W[N,K]^T + bias[N])
// BM=BN=64, BK=16, 256 threads, 4x4 per-thread microtile
// ---------------------------------------------------------------------------
#define BM 64
#define BN 64
#define BKK 16

template <bool RELU>
__global__ void __launch_bounds__(256) gemm_bias_kernel(
    const float* __restrict__ A, int lda,
    const float* __restrict__ W, int ldw,
    const float* __restrict__ bias,
    float* __restrict__ C, int ldc,
    int Mdim, int Ndim, int Kdim)
{
    __shared__ float As[BKK][BM + 1];
    __shared__ float Ws[BKK][BN + 1];

    const int tid = threadIdx.x;
    const int tx = tid & 15;         // 0..15
    const int ty = tid >> 4;         // 0..15
    const int bm = blockIdx.y * BM;
    const int bn = blockIdx.x * BN;

    // loader mapping: row = tid/4 (0..63), 4 consecutive k columns
    const int lrow = tid >> 2;
    const int lc4  = (tid & 3) * 4;

    float acc[4][4];
#pragma unroll
    for (int i = 0; i < 4; ++i)
#pragma unroll
        for (int j = 0; j < 4; ++j) acc[i][j] = 0.f;

    for (int k0 = 0; k0 < Kdim; k0 += BKK) {
        // ---- load A tile ----
        {
            int gr = bm + lrow;
            if (k0 + BKK <= Kdim && gr < Mdim) {
                float4 v = *reinterpret_cast<const float4*>(A + (size_t)gr * lda + k0 + lc4);
                As[lc4 + 0][lrow] = v.x;
                As[lc4 + 1][lrow] = v.y;
                As[lc4 + 2][lrow] = v.z;
                As[lc4 + 3][lrow] = v.w;
            } else {
#pragma unroll
                for (int q = 0; q < 4; ++q) {
                    int gc = k0 + lc4 + q;
                    As[lc4 + q][lrow] = (gr < Mdim && gc < Kdim)
                        ? A[(size_t)gr * lda + gc] : 0.f;
                }
            }
        }
        // ---- load W tile ----
        {
            int gn = bn + lrow;
            if (k0 + BKK <= Kdim && gn < Ndim) {
                float4 v = *reinterpret_cast<const float4*>(W + (size_t)gn * ldw + k0 + lc4);
                Ws[lc4 + 0][lrow] = v.x;
                Ws[lc4 + 1][lrow] = v.y;
                Ws[lc4 + 2][lrow] = v.z;
                Ws[lc4 + 3][lrow] = v.w;
            } else {
#pragma unroll
                for (int q = 0; q < 4; ++q) {
                    int gc = k0 + lc4 + q;
                    Ws[lc4 + q][lrow] = (gn < Ndim && gc < Kdim)
                        ? W[(size_t)gn * ldw + gc] : 0.f;
                }
            }
        }
        __syncthreads();

#pragma unroll
        for (int kk = 0; kk < BKK; ++kk) {
            float a[4], b[4];
#pragma unroll
            for (int i = 0; i < 4; ++i) a[i] = As[kk][ty * 4 + i];
#pragma unroll
            for (int j = 0; j < 4; ++j) b[j] = Ws[kk][tx * 4 + j];
#pragma unroll
            for (int i = 0; i < 4; ++i)
#pragma unroll
                for (int j = 0; j < 4; ++j) acc[i][j] += a[i] * b[j];
        }
        __syncthreads();
    }

#pragma unroll
    for (int i = 0; i < 4; ++i) {
        int gr = bm + ty * 4 + i;
        if (gr >= Mdim) continue;
#pragma unroll
        for (int j = 0; j < 4; ++j) {
            int gc = bn + tx * 4 + j;
            if (gc >= Ndim) continue;
            float v = acc[i][j] + bias[gc];
            if (RELU) v = fmaxf(v, 0.f);
            C[(size_t)gr * ldc + gc] = v;
        }
    }
}

// ---------------------------------------------------------------------------
// per-capsule L2 normalize: dst[n, k*16] (compact) from src (row stride ld)
// one thread per (node, capsule)
// ---------------------------------------------------------------------------
__global__ void normalize_kernel(const float* __restrict__ src, int ld,
                                 float* __restrict__ dst, int k)
{
    int idx = blockIdx.x * blockDim.x + threadIdx.x;
    int total = NNODES * k;
    if (idx >= total) return;
    int n_ = idx / k;
    int kk = idx - n_ * k;
    const float4* s = reinterpret_cast<const float4*>(src + (size_t)n_ * ld + kk * 16);
    float4 v[4];
    float sum = 0.f;
#pragma unroll
    for (int q = 0; q < 4; ++q) {
        v[q] = s[q];
        sum += v[q].x * v[q].x + v[q].y * v[q].y + v[q].z * v[q].z + v[q].w * v[q].w;
    }
    float inv = 1.f / fmaxf(sqrtf(sum), 1e-12f);
    float4* d = reinterpret_cast<float4*>(dst + (size_t)n_ * (k * 16) + kk * 16);
#pragma unroll
    for (int q = 0; q < 4; ++q) {
        float4 o;
        o.x = v[q].x * inv; o.y = v[q].y * inv;
        o.z = v[q].z * inv; o.w = v[q].w * inv;
        d[q] = o;
    }
}

// ---------------------------------------------------------------------------
// Routing: one CTA (128 threads) per node.
//  z[m][kk][dd] gathered once into smem; per-(m,kk) rows also cached in regs.
//  5 iterations of: p = z.u (regs+smem), softmax over kk (16 threads),
//  u = sum_m z*p + xself (smem z, conflict-free), capsule l2 via shfl.
// ---------------------------------------------------------------------------
template <int K>
__global__ void __launch_bounds__(128) routing_kernel(
    const float* __restrict__ xnorm,
    const int* __restrict__ nbid,
    float* __restrict__ outp)   // already offset to this layer's column block
{
    constexpr int KD = K * 16;
    constexpr int MK = 16 * K;
    const int n = blockIdx.x;
    const int tid = threadIdx.x;

    __shared__ float z[16 * KD];
    __shared__ float u[KD];
    __shared__ float ps[16 * 8];
    __shared__ int nb[16];

    if (tid < 16) nb[tid] = nbid[n * MNBR + tid];

    float xself = 0.f;
    if (tid < KD) {
        xself = xnorm[(size_t)n * KD + tid];
        u[tid] = xself;
    }
    __syncthreads();

    // gather neighbor rows (float4)
    {
        constexpr int Q = KD / 4;          // float4 per row
        constexpr int TOT = 16 * Q;
        float4* z4 = reinterpret_cast<float4*>(z);
        for (int i = tid; i < TOT; i += 128) {
            int j = i / Q;
            int w = i - j * Q;
            z4[i] = reinterpret_cast<const float4*>(xnorm + (size_t)nb[j] * KD)[w];
        }
    }
    __syncthreads();

    // register copy of this thread's (m, kk) z-row for the p-phase
    const int m_of = tid / K;
    const int k_of = tid - m_of * K;
    float4 zr[4];
    if (tid < MK) {
        const float4* zp = reinterpret_cast<const float4*>(z + m_of * KD + k_of * 16);
        zr[0] = zp[0]; zr[1] = zp[1]; zr[2] = zp[2]; zr[3] = zp[3];
    }
    const int kk = tid >> 4;

#pragma unroll
    for (int t = 0; t < 5; ++t) {
        // ---- agreement scores p[m][kk] = <z[m,kk,:], u[kk,:]> ----
        if (tid < MK) {
            const float4* up = reinterpret_cast<const float4*>(u + k_of * 16);
            float pv = 0.f;
#pragma unroll
            for (int q = 0; q < 4; ++q) {
                float4 uu = up[q];
                pv += zr[q].x * uu.x + zr[q].y * uu.y + zr[q].z * uu.z + zr[q].w * uu.w;
            }
            ps[m_of * 8 + k_of] = pv;
        }
        __syncthreads();

        // ---- softmax over capsules (one thread per m) ----
        if (tid < 16) {
            float mx = -1e30f;
#pragma unroll
            for (int c = 0; c < K; ++c) mx = fmaxf(mx, ps[tid * 8 + c]);
            float s = 0.f;
#pragma unroll
            for (int c = 0; c < K; ++c) {
                float e = __expf(ps[tid * 8 + c] - mx);
                ps[tid * 8 + c] = e;
                s += e;
            }
            float inv = 1.f / s;
#pragma unroll
            for (int c = 0; c < K; ++c) ps[tid * 8 + c] *= inv;
        }
        __syncthreads();

        // ---- aggregate u[kk][dd] = xself + sum_m z[m][kk][dd] * p[m][kk] ----
        float acc = 0.f;
        if (tid < KD) {
            acc = xself;
#pragma unroll
            for (int m = 0; m < 16; ++m)
                acc += z[m * KD + tid] * ps[m * 8 + kk];
        }

        if (t < 4) {
            // capsule L2 norm over 16 lanes (aligned groups within a warp)
            float sq = acc * acc;
            sq += __shfl_xor_sync(0xffffffffu, sq, 1);
            sq += __shfl_xor_sync(0xffffffffu, sq, 2);
            sq += __shfl_xor_sync(0xffffffffu, sq, 4);
            sq += __shfl_xor_sync(0xffffffffu, sq, 8);
            if (tid < KD) {
                float inv = 1.f / fmaxf(sqrtf(sq), 1e-12f);
                u[tid] = acc * inv;
            }
            __syncthreads();
        } else if (tid < KD) {
            outp[(size_t)n * OUTW + tid] = fmaxf(acc, 0.f);
        }
    }
}

// ---------------------------------------------------------------------------
// host orchestration
// ---------------------------------------------------------------------------
extern "C" void kernel_launch(void* const* d_in, const int* in_sizes, int n_in,
                              void* d_out, int out_size)
{
    (void)in_sizes; (void)n_in; (void)out_size;
    const float* feature = (const float*)d_in[0];
    const int*   nbid    = (const int*)d_in[1];
    const float* pca_w   = (const float*)d_in[2];
    const float* pca_b   = (const float*)d_in[3];
    const float* W[6]  = {nullptr, (const float*)d_in[4], (const float*)d_in[6],
                          (const float*)d_in[8], (const float*)d_in[10], (const float*)d_in[12]};
    const float* Bb[6] = {nullptr, (const float*)d_in[5], (const float*)d_in[7],
                          (const float*)d_in[9], (const float*)d_in[11], (const float*)d_in[13]};
    float* out = (float*)d_out;

    static const int caps[6]   = {8, 7, 6, 5, 4, 3};
    static const int coloff[7] = {0, 128, 256, 368, 464, 544, 608};

    float *lin, *xnorm;
    cudaGetSymbolAddress((void**)&lin, g_lin);
    cudaGetSymbolAddress((void**)&xnorm, g_xnorm);

    const int mblocks = (NNODES + BM - 1) / BM;   // 313

    // PCA: x0 = relu(feature @ pca_w.T + pca_b) -> out[:, 0:128]
    {
        dim3 grid((128 + BN - 1) / BN, mblocks);
        gemm_bias_kernel<true><<<grid, 256>>>(feature, FEAT, pca_w, FEAT, pca_b,
                                              out, OUTW, NNODES, 128, FEAT);
    }

    for (int i = 0; i < 6; ++i) {
        int k = caps[i];
        int kd = k * 16;
        const float* xin;
        int ld;
        if (i == 0) {
            xin = out; ld = OUTW;
        } else {
            int fin = caps[i - 1] * 16;
            dim3 grid((kd + BN - 1) / BN, mblocks);
            gemm_bias_kernel<false><<<grid, 256>>>(out + coloff[i], OUTW,
                                                   W[i], fin, Bb[i],
                                                   lin, kd, NNODES, kd, fin);
            xin = lin; ld = kd;
        }
        {
            int total = NNODES * k;
            normalize_kernel<<<(total + 255) / 256, 256>>>(xin, ld, xnorm, k);
        }
        float* dst = out + coloff[i + 1];
        switch (k) {
            case 8: routing_kernel<8><<<NNODES, 128>>>(xnorm, nbid, dst); break;
            case 7: routing_kernel<7><<<NNODES, 128>>>(xnorm, nbid, dst); break;
            case 6: routing_kernel<6><<<NNODES, 128>>>(xnorm, nbid, dst); break;
            case 5: routing_kernel<5><<<NNODES, 128>>>(xnorm, nbid, dst); break;
            case 4: routing_kernel<4><<<NNODES, 128>>>(xnorm, nbid, dst); break;
            case 3: routing_kernel<3><<<NNODES, 128>>>(xnorm, nbid, dst); break;
        }
    }
}

// round 2
// speedup vs baseline: 1.0611x; 1.0611x over previous
#include <cuda_runtime.h>
#include <cstdint>

// ---------------------------------------------------------------------------
// DisenGCN on GB300: fused GEMM(+bias+relu+capsule-normalize) + capsule routing
// N=20000, M=16 neighbors, FEAT=500, d=16, CAPS={8,7,6,5,4,3}, 5 routing iters
// ---------------------------------------------------------------------------

#define NNODES 20000
#define MNBR   16
#define FEAT   500
#define OUTW   656

// scratch (device global; no allocation allowed)
__device__ float g_xnorm[NNODES * 128];  // per-capsule L2-normalized x (compact KD)

// ---------------------------------------------------------------------------
// GEMM: val[M,N] = (relu?)(A[M,K] @ W[N,K]^T + bias[N])
//   epilogue: per-16-col-capsule L2 normalize -> xnorm (compact, row stride N)
//   WRITE_RAW: also store relu'd raw value to rawOut (PCA layer, jump connect)
// BM=128, BN=64, BKK=16, 256 threads, 8x4 per-thread microtile
// ---------------------------------------------------------------------------
#define BM 128
#define BN 64
#define BKK 16

template <bool WRITE_RAW>
__global__ void __launch_bounds__(256) gemm_norm_kernel(
    const float* __restrict__ A, int lda,
    const float* __restrict__ W, int ldw,
    const float* __restrict__ bias,
    float* __restrict__ rawOut, int ldo,
    float* __restrict__ xnorm,
    int Mdim, int Ndim, int Kdim)
{
    __shared__ float As[BKK][BM + 4];
    __shared__ float Ws[BKK][BN + 4];

    const int tid = threadIdx.x;
    const int tx = tid & 15;          // 0..15 -> 4 cols each
    const int ty = tid >> 4;          // 0..15 -> 8 rows each
    const int bm = blockIdx.y * BM;
    const int bn = blockIdx.x * BN;

    float acc[8][4];
#pragma unroll
    for (int i = 0; i < 8; ++i)
#pragma unroll
        for (int j = 0; j < 4; ++j) acc[i][j] = 0.f;

    for (int k0 = 0; k0 < Kdim; k0 += BKK) {
        const bool fullk = (k0 + BKK <= Kdim);
        // ---- load A tile: 512 float4, 2 per thread ----
#pragma unroll
        for (int l = 0; l < 2; ++l) {
            int idx = tid + l * 256;
            int r = idx >> 2;
            int c4 = (idx & 3) * 4;
            int gr = bm + r;
            if (fullk && gr < Mdim) {
                float4 v = *reinterpret_cast<const float4*>(A + (size_t)gr * lda + k0 + c4);
                As[c4 + 0][r] = v.x; As[c4 + 1][r] = v.y;
                As[c4 + 2][r] = v.z; As[c4 + 3][r] = v.w;
            } else {
#pragma unroll
                for (int q = 0; q < 4; ++q) {
                    int gc = k0 + c4 + q;
                    As[c4 + q][r] = (gr < Mdim && gc < Kdim)
                        ? A[(size_t)gr * lda + gc] : 0.f;
                }
            }
        }
        // ---- load W tile: 256 float4, 1 per thread ----
        {
            int r = tid >> 2;
            int c4 = (tid & 3) * 4;
            int gn = bn + r;
            if (fullk && gn < Ndim) {
                float4 v = *reinterpret_cast<const float4*>(W + (size_t)gn * ldw + k0 + c4);
                Ws[c4 + 0][r] = v.x; Ws[c4 + 1][r] = v.y;
                Ws[c4 + 2][r] = v.z; Ws[c4 + 3][r] = v.w;
            } else {
#pragma unroll
                for (int q = 0; q < 4; ++q) {
                    int gc = k0 + c4 + q;
                    Ws[c4 + q][r] = (gn < Ndim && gc < Kdim)
                        ? W[(size_t)gn * ldw + gc] : 0.f;
                }
            }
        }
        __syncthreads();

#pragma unroll
        for (int kk = 0; kk < BKK; ++kk) {
            float a[8], b[4];
#pragma unroll
            for (int i = 0; i < 8; ++i) a[i] = As[kk][ty * 8 + i];
#pragma unroll
            for (int j = 0; j < 4; ++j) b[j] = Ws[kk][tx * 4 + j];
#pragma unroll
            for (int i = 0; i < 8; ++i)
#pragma unroll
                for (int j = 0; j < 4; ++j) acc[i][j] += a[i] * b[j];
        }
        __syncthreads();
    }

    // ---- epilogue: bias (+relu) + per-capsule L2 normalize ----
    const int gc0 = bn + tx * 4;
    float bvals[4];
#pragma unroll
    for (int j = 0; j < 4; ++j) bvals[j] = (gc0 + j < Ndim) ? bias[gc0 + j] : 0.f;

#pragma unroll
    for (int i = 0; i < 8; ++i) {
        int gr = bm + ty * 8 + i;
        float v[4];
        float ssq = 0.f;
#pragma unroll
        for (int j = 0; j < 4; ++j) {
            float val = (gc0 + j < Ndim) ? acc[i][j] + bvals[j] : 0.f;
            if (WRITE_RAW) val = fmaxf(val, 0.f);
            v[j] = val;
            ssq += val * val;
        }
        // capsule (16 cols) spans 4 adjacent lanes (same ty, tx group of 4)
        ssq += __shfl_xor_sync(0xffffffffu, ssq, 1);
        ssq += __shfl_xor_sync(0xffffffffu, ssq, 2);
        float inv = 1.f / fmaxf(sqrtf(ssq), 1e-12f);
        if (gr < Mdim && gc0 < Ndim) {
            if (WRITE_RAW) {
                float4 o = make_float4(v[0], v[1], v[2], v[3]);
                *reinterpret_cast<float4*>(rawOut + (size_t)gr * ldo + gc0) = o;
            }
            float4 no = make_float4(v[0] * inv, v[1] * inv, v[2] * inv, v[3] * inv);
            *reinterpret_cast<float4*>(xnorm + (size_t)gr * Ndim + gc0) = no;
        }
    }
}

// ---------------------------------------------------------------------------
// Routing: one CTA per node. NT = max(KD, 16*P) threads, P = pow2 pad of K.
//  p-phase + softmax fully warp-level (shfl over padded capsule groups),
//  float4 aggregation, 2 barriers per iteration.
// ---------------------------------------------------------------------------
template <int K>
__global__ void __launch_bounds__((K > 4 || K * 16 > 64) ? 128 : 64) routing_kernel(
    const float* __restrict__ xnorm,
    const int* __restrict__ nbid,
    float* __restrict__ outp)   // already offset to this layer's column block
{
    constexpr int KD = K * 16;
    constexpr int P  = (K > 4) ? 8 : 4;            // padded capsule count (pow2)
    constexpr int NT = (KD > 16 * P) ? KD : 16 * P;
    constexpr int Q  = KD / 4;                      // float4 per neighbor row

    const int n = blockIdx.x;
    const int tid = threadIdx.x;

    __shared__ __align__(16) float z[16 * KD];
    __shared__ __align__(16) float u[KD];
    __shared__ float ps[16 * 8];
    __shared__ int nb[16];

    if (tid < 16) nb[tid] = nbid[n * MNBR + tid];

    // self row (normalized) as float4 per agg-thread; u init
    float4 xs4 = make_float4(0.f, 0.f, 0.f, 0.f);
    if (tid < Q) {
        xs4 = reinterpret_cast<const float4*>(xnorm + (size_t)n * KD)[tid];
        reinterpret_cast<float4*>(u)[tid] = xs4;
    }
    __syncthreads();

    // gather 16 neighbor rows into smem
    {
        float4* z4 = reinterpret_cast<float4*>(z);
        for (int i = tid; i < 16 * Q; i += NT) {
            int j = i / Q;
            int w = i - j * Q;
            z4[i] = reinterpret_cast<const float4*>(xnorm + (size_t)nb[j] * KD)[w];
        }
    }
    __syncthreads();

    // p-phase mapping: tid = m*P + k (NT == 16*P threads cover all)
    const int m_of = tid / P;
    const int k_of = tid - m_of * P;
    const bool valid = (k_of < K);

    // register cache of z[m][k][:]
    float4 zr[4];
    if (valid) {
        const float4* zp = reinterpret_cast<const float4*>(z + m_of * KD + k_of * 16);
        zr[0] = zp[0]; zr[1] = zp[1]; zr[2] = zp[2]; zr[3] = zp[3];
    }
    const int kk_a = tid >> 2;   // agg capsule: tid in [0, Q)

#pragma unroll
    for (int t = 0; t < 5; ++t) {
        // ---- agreement p[m][k] = <z[m,k,:], u[k,:]>, padded with -inf ----
        float p = -1e30f;
        if (valid) {
            const float4* up = reinterpret_cast<const float4*>(u + k_of * 16);
            p = 0.f;
#pragma unroll
            for (int q = 0; q < 4; ++q) {
                float4 uu = up[q];
                p += zr[q].x * uu.x + zr[q].y * uu.y + zr[q].z * uu.z + zr[q].w * uu.w;
            }
        }
        // ---- softmax over capsules via shfl within P-aligned groups ----
        float mx = p;
        mx = fmaxf(mx, __shfl_xor_sync(0xffffffffu, mx, 1));
        mx = fmaxf(mx, __shfl_xor_sync(0xffffffffu, mx, 2));
        if (P == 8) mx = fmaxf(mx, __shfl_xor_sync(0xffffffffu, mx, 4));
        float e = __expf(p - mx);
        float s = e;
        s += __shfl_xor_sync(0xffffffffu, s, 1);
        s += __shfl_xor_sync(0xffffffffu, s, 2);
        if (P == 8) s += __shfl_xor_sync(0xffffffffu, s, 4);
        float pr = e * (1.f / s);
        if (valid) ps[m_of * 8 + k_of] = pr;
        __syncthreads();

        // ---- aggregate: u[k][:] = xself + sum_m z[m][k][:] * p[m][k] ----
        float4 acc = xs4;
        float sq = 0.f;
        if (tid < Q) {
            const float4* z4 = reinterpret_cast<const float4*>(z);
#pragma unroll
            for (int m = 0; m < 16; ++m) {
                float4 zm = z4[m * Q + tid];
                float pm = ps[m * 8 + kk_a];
                acc.x += zm.x * pm; acc.y += zm.y * pm;
                acc.z += zm.z * pm; acc.w += zm.w * pm;
            }
            sq = acc.x * acc.x + acc.y * acc.y + acc.z * acc.z + acc.w * acc.w;
        }

        if (t < 4) {
            // capsule L2: 4 adjacent lanes hold one capsule
            sq += __shfl_xor_sync(0xffffffffu, sq, 1);
            sq += __shfl_xor_sync(0xffffffffu, sq, 2);
            if (tid < Q) {
                float inv = 1.f / fmaxf(sqrtf(sq), 1e-12f);
                float4 o = make_float4(acc.x * inv, acc.y * inv, acc.z * inv, acc.w * inv);
                reinterpret_cast<float4*>(u)[tid] = o;
            }
            __syncthreads();
        } else if (tid < Q) {
            float4 o = make_float4(fmaxf(acc.x, 0.f), fmaxf(acc.y, 0.f),
                                   fmaxf(acc.z, 0.f), fmaxf(acc.w, 0.f));
            *reinterpret_cast<float4*>(outp + (size_t)n * OUTW + tid * 4) = o;
        }
    }
}

// ---------------------------------------------------------------------------
// host orchestration
// ---------------------------------------------------------------------------
extern "C" void kernel_launch(void* const* d_in, const int* in_sizes, int n_in,
                              void* d_out, int out_size)
{
    (void)in_sizes; (void)n_in; (void)out_size;
    const float* feature = (const float*)d_in[0];
    const int*   nbid    = (const int*)d_in[1];
    const float* pca_w   = (const float*)d_in[2];
    const float* pca_b   = (const float*)d_in[3];
    const float* W[6]  = {nullptr, (const float*)d_in[4], (const float*)d_in[6],
                          (const float*)d_in[8], (const float*)d_in[10], (const float*)d_in[12]};
    const float* Bb[6] = {nullptr, (const float*)d_in[5], (const float*)d_in[7],
                          (const float*)d_in[9], (const float*)d_in[11], (const float*)d_in[13]};
    float* out = (float*)d_out;

    static const int caps[6]   = {8, 7, 6, 5, 4, 3};
    static const int coloff[7] = {0, 128, 256, 368, 464, 544, 608};

    float* xnorm;
    cudaGetSymbolAddress((void**)&xnorm, g_xnorm);

    const int mblocks = (NNODES + BM - 1) / BM;   // 157

    // PCA: x0 = relu(feature @ pca_w.T + pca_b) -> out[:,0:128] + xnorm
    {
        dim3 grid((128 + BN - 1) / BN, mblocks);
        gemm_norm_kernel<true><<<grid, 256>>>(feature, FEAT, pca_w, FEAT, pca_b,
                                              out, OUTW, xnorm, NNODES, 128, FEAT);
    }

    for (int i = 0; i < 6; ++i) {
        int k = caps[i];
        int kd = k * 16;
        if (i > 0) {
            int fin = caps[i - 1] * 16;
            dim3 grid((kd + BN - 1) / BN, mblocks);
            gemm_norm_kernel<false><<<grid, 256>>>(out + coloff[i], OUTW,
                                                   W[i], fin, Bb[i],
                                                   nullptr, 0, xnorm,
                                                   NNODES, kd, fin);
        }
        float* dst = out + coloff[i + 1];
        switch (k) {
            case 8: routing_kernel<8><<<NNODES, 128>>>(xnorm, nbid, dst); break;
            case 7: routing_kernel<7><<<NNODES, 128>>>(xnorm, nbid, dst); break;
            case 6: routing_kernel<6><<<NNODES, 128>>>(xnorm, nbid, dst); break;
            case 5: routing_kernel<5><<<NNODES, 128>>>(xnorm, nbid, dst); break;
            case 4: routing_kernel<4><<<NNODES, 64>>>(xnorm, nbid, dst); break;
            case 3: routing_kernel<3><<<NNODES, 64>>>(xnorm, nbid, dst); break;
        }
    }
}

// round 3
// speedup vs baseline: 1.2985x; 1.2237x over previous
#include <cuda_runtime.h>
#include <cstdint>

// ---------------------------------------------------------------------------
// DisenGCN on GB300: fused GEMM(+bias+relu+capsule-normalize) + capsule routing
// N=20000, M=16 neighbors, FEAT=500, d=16, CAPS={8,7,6,5,4,3}, 5 routing iters
// ---------------------------------------------------------------------------

#define NNODES 20000
#define MNBR   16
#define FEAT   500
#define OUTW   656

// scratch (device global; no allocation allowed)
__device__ float g_xnorm[NNODES * 128];  // per-capsule L2-normalized x (compact KD)

// ---------------------------------------------------------------------------
// GEMM: val[M,N] = (relu?)(A[M,K] @ W[N,K]^T + bias[N])
//   epilogue: per-16-col-capsule L2 normalize -> xnorm (compact, row stride N)
//   WRITE_RAW: also store relu'd raw value to rawOut (PCA layer, jump connect)
// BM=128, BN=64, BKK=16, 256 threads, 8x4 per-thread microtile
// ---------------------------------------------------------------------------
#define BM 128
#define BN 64
#define BKK 16

template <bool WRITE_RAW>
__global__ void __launch_bounds__(256) gemm_norm_kernel(
    const float* __restrict__ A, int lda,
    const float* __restrict__ W, int ldw,
    const float* __restrict__ bias,
    float* __restrict__ rawOut, int ldo,
    float* __restrict__ xnorm,
    int Mdim, int Ndim, int Kdim)
{
    __shared__ float As[BKK][BM + 4];
    __shared__ float Ws[BKK][BN + 4];

    const int tid = threadIdx.x;
    const int tx = tid & 15;          // 0..15 -> 4 cols each
    const int ty = tid >> 4;          // 0..15 -> 8 rows each
    const int bm = blockIdx.y * BM;
    const int bn = blockIdx.x * BN;

    float acc[8][4];
#pragma unroll
    for (int i = 0; i < 8; ++i)
#pragma unroll
        for (int j = 0; j < 4; ++j) acc[i][j] = 0.f;

    for (int k0 = 0; k0 < Kdim; k0 += BKK) {
        const bool fullk = (k0 + BKK <= Kdim);
        // ---- load A tile: 512 float4, 2 per thread ----
#pragma unroll
        for (int l = 0; l < 2; ++l) {
            int idx = tid + l * 256;
            int r = idx >> 2;
            int c4 = (idx & 3) * 4;
            int gr = bm + r;
            if (fullk && gr < Mdim) {
                float4 v = *reinterpret_cast<const float4*>(A + (size_t)gr * lda + k0 + c4);
                As[c4 + 0][r] = v.x; As[c4 + 1][r] = v.y;
                As[c4 + 2][r] = v.z; As[c4 + 3][r] = v.w;
            } else {
#pragma unroll
                for (int q = 0; q < 4; ++q) {
                    int gc = k0 + c4 + q;
                    As[c4 + q][r] = (gr < Mdim && gc < Kdim)
                        ? A[(size_t)gr * lda + gc] : 0.f;
                }
            }
        }
        // ---- load W tile: 256 float4, 1 per thread ----
        {
            int r = tid >> 2;
            int c4 = (tid & 3) * 4;
            int gn = bn + r;
            if (fullk && gn < Ndim) {
                float4 v = *reinterpret_cast<const float4*>(W + (size_t)gn * ldw + k0 + c4);
                Ws[c4 + 0][r] = v.x; Ws[c4 + 1][r] = v.y;
                Ws[c4 + 2][r] = v.z; Ws[c4 + 3][r] = v.w;
            } else {
#pragma unroll
                for (int q = 0; q < 4; ++q) {
                    int gc = k0 + c4 + q;
                    Ws[c4 + q][r] = (gn < Ndim && gc < Kdim)
                        ? W[(size_t)gn * ldw + gc] : 0.f;
                }
            }
        }
        __syncthreads();

#pragma unroll
        for (int kk = 0; kk < BKK; ++kk) {
            float a[8], b[4];
#pragma unroll
            for (int i = 0; i < 8; ++i) a[i] = As[kk][ty * 8 + i];
#pragma unroll
            for (int j = 0; j < 4; ++j) b[j] = Ws[kk][tx * 4 + j];
#pragma unroll
            for (int i = 0; i < 8; ++i)
#pragma unroll
                for (int j = 0; j < 4; ++j) acc[i][j] += a[i] * b[j];
        }
        __syncthreads();
    }

    // ---- epilogue: bias (+relu) + per-capsule L2 normalize ----
    const int gc0 = bn + tx * 4;
    float bvals[4];
#pragma unroll
    for (int j = 0; j < 4; ++j) bvals[j] = (gc0 + j < Ndim) ? bias[gc0 + j] : 0.f;

#pragma unroll
    for (int i = 0; i < 8; ++i) {
        int gr = bm + ty * 8 + i;
        float v[4];
        float ssq = 0.f;
#pragma unroll
        for (int j = 0; j < 4; ++j) {
            float val = (gc0 + j < Ndim) ? acc[i][j] + bvals[j] : 0.f;
            if (WRITE_RAW) val = fmaxf(val, 0.f);
            v[j] = val;
            ssq += val * val;
        }
        // capsule (16 cols) spans 4 adjacent lanes (same ty, tx group of 4)
        ssq += __shfl_xor_sync(0xffffffffu, ssq, 1);
        ssq += __shfl_xor_sync(0xffffffffu, ssq, 2);
        float inv = 1.f / fmaxf(sqrtf(ssq), 1e-12f);
        if (gr < Mdim && gc0 < Ndim) {
            if (WRITE_RAW) {
                float4 o = make_float4(v[0], v[1], v[2], v[3]);
                *reinterpret_cast<float4*>(rawOut + (size_t)gr * ldo + gc0) = o;
            }
            float4 no = make_float4(v[0] * inv, v[1] * inv, v[2] * inv, v[3] * inv);
            *reinterpret_cast<float4*>(xnorm + (size_t)gr * Ndim + gc0) = no;
        }
    }
}

// ---------------------------------------------------------------------------
// Routing: one CTA per node, NT = 16*P threads (P = pow2 pad of K).
//  Phase A (scores): tid = m*P + k; z row cached in regs; softmax via shfl.
//  Phase B (agg):    tid = q*4 + g; each thread owns 4 m's (z in regs),
//                    reduce over g via shfl_xor 1,2; capsule ssq via 4,8.
//  Padded smem (u stride 20, ps stride 9) -> bank-conflict free.
// ---------------------------------------------------------------------------
template <int K>
__global__ void __launch_bounds__((K > 4) ? 128 : 64) routing_kernel(
    const float* __restrict__ xnorm,
    const int* __restrict__ nbid,
    float* __restrict__ outp)   // already offset to this layer's column block
{
    constexpr int P  = (K > 4) ? 8 : 4;    // padded capsule count (pow2)
    constexpr int NT = 16 * P;             // threads
    constexpr int KD = K * 16;
    constexpr int Q  = K * 4;              // float4 per node row
    constexpr int UP = 20;                 // u row stride (floats)
    constexpr int PSP = 9;                 // ps row stride (floats)

    const int n = blockIdx.x;
    const int tid = threadIdx.x;

    __shared__ __align__(16) float z[16 * KD];
    __shared__ __align__(16) float u[8 * UP];
    __shared__ float ps[16 * PSP];

    // init u = normalized self row (padded layout)
    if (tid < Q) {
        float4 v = reinterpret_cast<const float4*>(xnorm + (size_t)n * KD)[tid];
        *reinterpret_cast<float4*>(u + (tid >> 2) * UP + (tid & 3) * 4) = v;
    }

    // gather 16 neighbor rows into z (neighbor ids straight from L1/L2)
    {
        float4* z4 = reinterpret_cast<float4*>(z);
        for (int i = tid; i < 16 * Q; i += NT) {
            int j = i / Q;
            int w = i - j * Q;
            int nbj = nbid[n * MNBR + j];
            z4[i] = reinterpret_cast<const float4*>(xnorm + (size_t)nbj * KD)[w];
        }
    }
    __syncthreads();

    // ---- phase-A mapping + reg cache: tid = mA*P + kA ----
    const int mA = tid / P;
    const int kA = tid & (P - 1);
    const bool validA = (kA < K);
    const int kAc = validA ? kA : (K - 1);
    float4 zp[4];
    {
        const float4* src = reinterpret_cast<const float4*>(z + mA * KD + kAc * 16);
        zp[0] = src[0]; zp[1] = src[1]; zp[2] = src[2]; zp[3] = src[3];
    }

    // ---- phase-B mapping + reg cache: tid = qB*4 + gB ----
    const int qB = tid >> 2;
    const int gB = tid & 3;
    const bool validB = (tid < KD);
    const int qc = validB ? qB : (Q - 1);
    const int kB = qc >> 2;                // capsule of this q
    float4 za[4];
#pragma unroll
    for (int j = 0; j < 4; ++j)
        za[j] = reinterpret_cast<const float4*>(z)[(4 * gB + j) * Q + qc];
    // self slice for aggregation (added once, after g-reduction)
    float4 xs4 = *reinterpret_cast<const float4*>(u + kB * UP + (qc & 3) * 4);

#pragma unroll
    for (int t = 0; t < 5; ++t) {
        // ---- A: agreement p[m][k] = <z[m,k,:], u[k,:]> ----
        float p;
        {
            const float4* up = reinterpret_cast<const float4*>(u + kAc * UP);
            float pv = 0.f;
#pragma unroll
            for (int q = 0; q < 4; ++q) {
                float4 uu = up[q];
                pv += zp[q].x * uu.x + zp[q].y * uu.y + zp[q].z * uu.z + zp[q].w * uu.w;
            }
            p = validA ? pv : -1e30f;
        }
        // softmax over capsules within P-aligned lane groups
        float mx = p;
        mx = fmaxf(mx, __shfl_xor_sync(0xffffffffu, mx, 1));
        mx = fmaxf(mx, __shfl_xor_sync(0xffffffffu, mx, 2));
        if (P == 8) mx = fmaxf(mx, __shfl_xor_sync(0xffffffffu, mx, 4));
        float e = __expf(p - mx);
        float s = e;
        s += __shfl_xor_sync(0xffffffffu, s, 1);
        s += __shfl_xor_sync(0xffffffffu, s, 2);
        if (P == 8) s += __shfl_xor_sync(0xffffffffu, s, 4);
        float pr = __fdividef(e, s);
        if (validA) ps[mA * PSP + kA] = pr;
        __syncthreads();

        // ---- B: u[k][:] = xself + sum_m z[m][k][:] * p[m][k] ----
        float4 acc = make_float4(0.f, 0.f, 0.f, 0.f);
#pragma unroll
        for (int j = 0; j < 4; ++j) {
            float pm = ps[(4 * gB + j) * PSP + kB];
            acc.x += za[j].x * pm; acc.y += za[j].y * pm;
            acc.z += za[j].z * pm; acc.w += za[j].w * pm;
        }
        // reduce over the 4 m-groups (adjacent lanes)
#pragma unroll
        for (int d = 1; d <= 2; d <<= 1) {
            acc.x += __shfl_xor_sync(0xffffffffu, acc.x, d);
            acc.y += __shfl_xor_sync(0xffffffffu, acc.y, d);
            acc.z += __shfl_xor_sync(0xffffffffu, acc.z, d);
            acc.w += __shfl_xor_sync(0xffffffffu, acc.w, d);
        }
        acc.x += xs4.x; acc.y += xs4.y; acc.z += xs4.z; acc.w += xs4.w;

        if (t < 4) {
            float sq = acc.x * acc.x + acc.y * acc.y + acc.z * acc.z + acc.w * acc.w;
            sq += __shfl_xor_sync(0xffffffffu, sq, 4);
            sq += __shfl_xor_sync(0xffffffffu, sq, 8);
            float inv = rsqrtf(fmaxf(sq, 1e-24f));
            if (validB && gB == 0) {
                float4 o = make_float4(acc.x * inv, acc.y * inv, acc.z * inv, acc.w * inv);
                *reinterpret_cast<float4*>(u + kB * UP + (qB & 3) * 4) = o;
            }
            __syncthreads();
        } else if (validB && gB == 0) {
            float4 o = make_float4(fmaxf(acc.x, 0.f), fmaxf(acc.y, 0.f),
                                   fmaxf(acc.z, 0.f), fmaxf(acc.w, 0.f));
            *reinterpret_cast<float4*>(outp + (size_t)n * OUTW + qB * 4) = o;
        }
    }
}

// ---------------------------------------------------------------------------
// host orchestration
// ---------------------------------------------------------------------------
extern "C" void kernel_launch(void* const* d_in, const int* in_sizes, int n_in,
                              void* d_out, int out_size)
{
    (void)in_sizes; (void)n_in; (void)out_size;
    const float* feature = (const float*)d_in[0];
    const int*   nbid    = (const int*)d_in[1];
    const float* pca_w   = (const float*)d_in[2];
    const float* pca_b   = (const float*)d_in[3];
    const float* W[6]  = {nullptr, (const float*)d_in[4], (const float*)d_in[6],
                          (const float*)d_in[8], (const float*)d_in[10], (const float*)d_in[12]};
    const float* Bb[6] = {nullptr, (const float*)d_in[5], (const float*)d_in[7],
                          (const float*)d_in[9], (const float*)d_in[11], (const float*)d_in[13]};
    float* out = (float*)d_out;

    static const int caps[6]   = {8, 7, 6, 5, 4, 3};
    static const int coloff[7] = {0, 128, 256, 368, 464, 544, 608};

    float* xnorm;
    cudaGetSymbolAddress((void**)&xnorm, g_xnorm);

    const int mblocks = (NNODES + BM - 1) / BM;   // 157

    // PCA: x0 = relu(feature @ pca_w.T + pca_b) -> out[:,0:128] + xnorm
    {
        dim3 grid((128 + BN - 1) / BN, mblocks);
        gemm_norm_kernel<true><<<grid, 256>>>(feature, FEAT, pca_w, FEAT, pca_b,
                                              out, OUTW, xnorm, NNODES, 128, FEAT);
    }

    for (int i = 0; i < 6; ++i) {
        int k = caps[i];
        int kd = k * 16;
        if (i > 0) {
            int fin = caps[i - 1] * 16;
            dim3 grid((kd + BN - 1) / BN, mblocks);
            gemm_norm_kernel<false><<<grid, 256>>>(out + coloff[i], OUTW,
                                                   W[i], fin, Bb[i],
                                                   nullptr, 0, xnorm,
                                                   NNODES, kd, fin);
        }
        float* dst = out + coloff[i + 1];
        switch (k) {
            case 8: routing_kernel<8><<<NNODES, 128>>>(xnorm, nbid, dst); break;
            case 7: routing_kernel<7><<<NNODES, 128>>>(xnorm, nbid, dst); break;
            case 6: routing_kernel<6><<<NNODES, 128>>>(xnorm, nbid, dst); break;
            case 5: routing_kernel<5><<<NNODES, 128>>>(xnorm, nbid, dst); break;
            case 4: routing_kernel<4><<<NNODES, 64>>>(xnorm, nbid, dst); break;
            case 3: routing_kernel<3><<<NNODES, 64>>>(xnorm, nbid, dst); break;
        }
    }
}

// round 4
// speedup vs baseline: 1.3068x; 1.0064x over previous
#include <cuda_runtime.h>
#include <cstdint>

// ---------------------------------------------------------------------------
// DisenGCN on GB300: fused GEMM(+bias+relu+capsule-normalize) + capsule routing
// N=20000, M=16 neighbors, FEAT=500, d=16, CAPS={8,7,6,5,4,3}, 5 routing iters
// ---------------------------------------------------------------------------

#define NNODES 20000
#define MNBR   16
#define FEAT   500
#define OUTW   656

// scratch (device global; no allocation allowed)
__device__ float g_xnorm[NNODES * 128];  // per-capsule L2-normalized x (compact KD)

// ---------------------------------------------------------------------------
// GEMM: val[M,N] = (relu?)(A[M,K] @ W[N,K]^T + bias[N])
//   epilogue: per-16-col-capsule L2 normalize -> xnorm (compact, row stride N)
//   WRITE_RAW: also store relu'd raw value to rawOut (PCA layer, jump connect)
// BM=128, BN=64, BKK=16, 256 threads, 8x4 per-thread microtile
// ---------------------------------------------------------------------------
#define BM 128
#define BN 64
#define BKK 16

template <bool WRITE_RAW>
__global__ void __launch_bounds__(256) gemm_norm_kernel(
    const float* __restrict__ A, int lda,
    const float* __restrict__ W, int ldw,
    const float* __restrict__ bias,
    float* __restrict__ rawOut, int ldo,
    float* __restrict__ xnorm,
    int Mdim, int Ndim, int Kdim)
{
    __shared__ float As[BKK][BM + 4];
    __shared__ float Ws[BKK][BN + 4];

    const int tid = threadIdx.x;
    const int tx = tid & 15;          // 0..15 -> 4 cols each
    const int ty = tid >> 4;          // 0..15 -> 8 rows each
    const int bm = blockIdx.y * BM;
    const int bn = blockIdx.x * BN;

    float acc[8][4];
#pragma unroll
    for (int i = 0; i < 8; ++i)
#pragma unroll
        for (int j = 0; j < 4; ++j) acc[i][j] = 0.f;

    for (int k0 = 0; k0 < Kdim; k0 += BKK) {
        const bool fullk = (k0 + BKK <= Kdim);
        // ---- load A tile: 512 float4, 2 per thread ----
#pragma unroll
        for (int l = 0; l < 2; ++l) {
            int idx = tid + l * 256;
            int r = idx >> 2;
            int c4 = (idx & 3) * 4;
            int gr = bm + r;
            if (fullk && gr < Mdim) {
                float4 v = *reinterpret_cast<const float4*>(A + (size_t)gr * lda + k0 + c4);
                As[c4 + 0][r] = v.x; As[c4 + 1][r] = v.y;
                As[c4 + 2][r] = v.z; As[c4 + 3][r] = v.w;
            } else {
#pragma unroll
                for (int q = 0; q < 4; ++q) {
                    int gc = k0 + c4 + q;
                    As[c4 + q][r] = (gr < Mdim && gc < Kdim)
                        ? A[(size_t)gr * lda + gc] : 0.f;
                }
            }
        }
        // ---- load W tile: 256 float4, 1 per thread ----
        {
            int r = tid >> 2;
            int c4 = (tid & 3) * 4;
            int gn = bn + r;
            if (fullk && gn < Ndim) {
                float4 v = *reinterpret_cast<const float4*>(W + (size_t)gn * ldw + k0 + c4);
                Ws[c4 + 0][r] = v.x; Ws[c4 + 1][r] = v.y;
                Ws[c4 + 2][r] = v.z; Ws[c4 + 3][r] = v.w;
            } else {
#pragma unroll
                for (int q = 0; q < 4; ++q) {
                    int gc = k0 + c4 + q;
                    Ws[c4 + q][r] = (gn < Ndim && gc < Kdim)
                        ? W[(size_t)gn * ldw + gc] : 0.f;
                }
            }
        }
        __syncthreads();

#pragma unroll
        for (int kk = 0; kk < BKK; ++kk) {
            float a[8], b[4];
#pragma unroll
            for (int i = 0; i < 8; ++i) a[i] = As[kk][ty * 8 + i];
#pragma unroll
            for (int j = 0; j < 4; ++j) b[j] = Ws[kk][tx * 4 + j];
#pragma unroll
            for (int i = 0; i < 8; ++i)
#pragma unroll
                for (int j = 0; j < 4; ++j) acc[i][j] += a[i] * b[j];
        }
        __syncthreads();
    }

    // ---- epilogue: bias (+relu) + per-capsule L2 normalize ----
    const int gc0 = bn + tx * 4;
    float bvals[4];
#pragma unroll
    for (int j = 0; j < 4; ++j) bvals[j] = (gc0 + j < Ndim) ? bias[gc0 + j] : 0.f;

#pragma unroll
    for (int i = 0; i < 8; ++i) {
        int gr = bm + ty * 8 + i;
        float v[4];
        float ssq = 0.f;
#pragma unroll
        for (int j = 0; j < 4; ++j) {
            float val = (gc0 + j < Ndim) ? acc[i][j] + bvals[j] : 0.f;
            if (WRITE_RAW) val = fmaxf(val, 0.f);
            v[j] = val;
            ssq += val * val;
        }
        // capsule (16 cols) spans 4 adjacent lanes (same ty, tx group of 4)
        ssq += __shfl_xor_sync(0xffffffffu, ssq, 1);
        ssq += __shfl_xor_sync(0xffffffffu, ssq, 2);
        float inv = 1.f / fmaxf(sqrtf(ssq), 1e-12f);
        if (gr < Mdim && gc0 < Ndim) {
            if (WRITE_RAW) {
                float4 o = make_float4(v[0], v[1], v[2], v[3]);
                *reinterpret_cast<float4*>(rawOut + (size_t)gr * ldo + gc0) = o;
            }
            float4 no = make_float4(v[0] * inv, v[1] * inv, v[2] * inv, v[3] * inv);
            *reinterpret_cast<float4*>(xnorm + (size_t)gr * Ndim + gc0) = no;
        }
    }
}

// ---------------------------------------------------------------------------
// Routing: one CTA per node, NT = 16*P threads (P = pow2 pad of K).
//  Phase A (scores): tid = m*P + k; z row cached in regs; softmax WITHOUT the
//    max-subtraction (scores are cosines in [-1,1], exp cannot overflow),
//    so only the sum butterfly remains (3 shfl for P=8, 2 for P=4).
//  Phase B (agg):    tid = q*2 + g; each thread owns 8 m's (z in regs),
//    reduce over g via shfl_xor 1 (float4); capsule ssq via xor 2,4.
//  Padded smem (u stride 20, ps stride 9) -> bank-conflict free.
// ---------------------------------------------------------------------------
template <int K>
__global__ void __launch_bounds__((K > 4) ? 128 : 64) routing_kernel(
    const float* __restrict__ xnorm,
    const int* __restrict__ nbid,
    float* __restrict__ outp)   // already offset to this layer's column block
{
    constexpr int P  = (K > 4) ? 8 : 4;    // padded capsule count (pow2)
    constexpr int NT = 16 * P;             // threads
    constexpr int KD = K * 16;
    constexpr int Q  = K * 4;              // float4 per node row
    constexpr int UP = 20;                 // u row stride (floats)
    constexpr int PSP = 9;                 // ps row stride (floats)

    const int n = blockIdx.x;
    const int tid = threadIdx.x;

    __shared__ __align__(16) float z[16 * KD];
    __shared__ __align__(16) float u[8 * UP];
    __shared__ float ps[16 * PSP];

    // init u = normalized self row (padded layout)
    if (tid < Q) {
        float4 v = reinterpret_cast<const float4*>(xnorm + (size_t)n * KD)[tid];
        *reinterpret_cast<float4*>(u + (tid >> 2) * UP + (tid & 3) * 4) = v;
    }

    // gather 16 neighbor rows into z (neighbor ids straight from L1/L2)
    {
        float4* z4 = reinterpret_cast<float4*>(z);
        for (int i = tid; i < 16 * Q; i += NT) {
            int j = i / Q;
            int w = i - j * Q;
            int nbj = nbid[n * MNBR + j];
            z4[i] = reinterpret_cast<const float4*>(xnorm + (size_t)nbj * KD)[w];
        }
    }
    __syncthreads();

    // ---- phase-A mapping + reg cache: tid = mA*P + kA ----
    const int mA = tid / P;
    const int kA = tid & (P - 1);
    const bool validA = (kA < K);
    const int kAc = validA ? kA : (K - 1);
    float4 zp[4];
    {
        const float4* src = reinterpret_cast<const float4*>(z + mA * KD + kAc * 16);
        zp[0] = src[0]; zp[1] = src[1]; zp[2] = src[2]; zp[3] = src[3];
    }

    // ---- phase-B mapping + reg cache: tid = qB*2 + gB (8 m's per thread) ----
    const int qB = tid >> 1;
    const int gB = tid & 1;
    const bool validB = (tid < 2 * Q);
    const int qc = validB ? qB : (Q - 1);
    const int kB = qc >> 2;                // capsule of this q
    float4 za[8];
#pragma unroll
    for (int j = 0; j < 8; ++j)
        za[j] = reinterpret_cast<const float4*>(z)[(8 * gB + j) * Q + qc];
    // self slice for aggregation (added once, after g-reduction)
    float4 xs4 = *reinterpret_cast<const float4*>(u + kB * UP + (qc & 3) * 4);

#pragma unroll
    for (int t = 0; t < 5; ++t) {
        // ---- A: agreement p[m][k] = <z[m,k,:], u[k,:]> ----
        float p;
        {
            const float4* up = reinterpret_cast<const float4*>(u + kAc * UP);
            float pv = 0.f;
#pragma unroll
            for (int q = 0; q < 4; ++q) {
                float4 uu = up[q];
                pv += zp[q].x * uu.x + zp[q].y * uu.y + zp[q].z * uu.z + zp[q].w * uu.w;
            }
            p = validA ? pv : -1e30f;
        }
        // softmax over capsules (no max-sub: |p|<=1, padding exp -> 0)
        float e = __expf(p);
        float s = e;
        s += __shfl_xor_sync(0xffffffffu, s, 1);
        s += __shfl_xor_sync(0xffffffffu, s, 2);
        if (P == 8) s += __shfl_xor_sync(0xffffffffu, s, 4);
        float pr = __fdividef(e, s);
        if (validA) ps[mA * PSP + kA] = pr;
        __syncthreads();

        // ---- B: u[k][:] = xself + sum_m z[m][k][:] * p[m][k] ----
        float4 acc = make_float4(0.f, 0.f, 0.f, 0.f);
#pragma unroll
        for (int j = 0; j < 8; ++j) {
            float pm = ps[(8 * gB + j) * PSP + kB];
            acc.x += za[j].x * pm; acc.y += za[j].y * pm;
            acc.z += za[j].z * pm; acc.w += za[j].w * pm;
        }
        // reduce over the 2 m-groups (adjacent lanes)
        acc.x += __shfl_xor_sync(0xffffffffu, acc.x, 1);
        acc.y += __shfl_xor_sync(0xffffffffu, acc.y, 1);
        acc.z += __shfl_xor_sync(0xffffffffu, acc.z, 1);
        acc.w += __shfl_xor_sync(0xffffffffu, acc.w, 1);
        acc.x += xs4.x; acc.y += xs4.y; acc.z += xs4.z; acc.w += xs4.w;

        if (t < 4) {
            // capsule L2: capsule spans 8 adjacent lanes (4 chunks x 2 dup)
            float sq = acc.x * acc.x + acc.y * acc.y + acc.z * acc.z + acc.w * acc.w;
            sq += __shfl_xor_sync(0xffffffffu, sq, 2);
            sq += __shfl_xor_sync(0xffffffffu, sq, 4);
            float inv = rsqrtf(fmaxf(sq, 1e-24f));
            if (validB && gB == 0) {
                float4 o = make_float4(acc.x * inv, acc.y * inv, acc.z * inv, acc.w * inv);
                *reinterpret_cast<float4*>(u + kB * UP + (qB & 3) * 4) = o;
            }
            __syncthreads();
        } else if (validB && gB == 0) {
            float4 o = make_float4(fmaxf(acc.x, 0.f), fmaxf(acc.y, 0.f),
                                   fmaxf(acc.z, 0.f), fmaxf(acc.w, 0.f));
            *reinterpret_cast<float4*>(outp + (size_t)n * OUTW + qB * 4) = o;
        }
    }
}

// ---------------------------------------------------------------------------
// host orchestration
// ---------------------------------------------------------------------------
extern "C" void kernel_launch(void* const* d_in, const int* in_sizes, int n_in,
                              void* d_out, int out_size)
{
    (void)in_sizes; (void)n_in; (void)out_size;
    const float* feature = (const float*)d_in[0];
    const int*   nbid    = (const int*)d_in[1];
    const float* pca_w   = (const float*)d_in[2];
    const float* pca_b   = (const float*)d_in[3];
    const float* W[6]  = {nullptr, (const float*)d_in[4], (const float*)d_in[6],
                          (const float*)d_in[8], (const float*)d_in[10], (const float*)d_in[12]};
    const float* Bb[6] = {nullptr, (const float*)d_in[5], (const float*)d_in[7],
                          (const float*)d_in[9], (const float*)d_in[11], (const float*)d_in[13]};
    float* out = (float*)d_out;

    static const int caps[6]   = {8, 7, 6, 5, 4, 3};
    static const int coloff[7] = {0, 128, 256, 368, 464, 544, 608};

    float* xnorm;
    cudaGetSymbolAddress((void**)&xnorm, g_xnorm);

    const int mblocks = (NNODES + BM - 1) / BM;   // 157

    // PCA: x0 = relu(feature @ pca_w.T + pca_b) -> out[:,0:128] + xnorm
    {
        dim3 grid((128 + BN - 1) / BN, mblocks);
        gemm_norm_kernel<true><<<grid, 256>>>(feature, FEAT, pca_w, FEAT, pca_b,
                                              out, OUTW, xnorm, NNODES, 128, FEAT);
    }

    for (int i = 0; i < 6; ++i) {
        int k = caps[i];
        int kd = k * 16;
        if (i > 0) {
            int fin = caps[i - 1] * 16;
            dim3 grid((kd + BN - 1) / BN, mblocks);
            gemm_norm_kernel<false><<<grid, 256>>>(out + coloff[i], OUTW,
                                                   W[i], fin, Bb[i],
                                                   nullptr, 0, xnorm,
                                                   NNODES, kd, fin);
        }
        float* dst = out + coloff[i + 1];
        switch (k) {
            case 8: routing_kernel<8><<<NNODES, 128>>>(xnorm, nbid, dst); break;
            case 7: routing_kernel<7><<<NNODES, 128>>>(xnorm, nbid, dst); break;
            case 6: routing_kernel<6><<<NNODES, 128>>>(xnorm, nbid, dst); break;
            case 5: routing_kernel<5><<<NNODES, 128>>>(xnorm, nbid, dst); break;
            case 4: routing_kernel<4><<<NNODES, 64>>>(xnorm, nbid, dst); break;
            case 3: routing_kernel<3><<<NNODES, 64>>>(xnorm, nbid, dst); break;
        }
    }
}

// round 5
// speedup vs baseline: 1.3377x; 1.0237x over previous
#include <cuda_runtime.h>
#include <cstdint>

// ---------------------------------------------------------------------------
// DisenGCN on GB300: fused GEMM(+bias+relu+capsule-normalize) + capsule routing
// N=20000, M=16 neighbors, FEAT=500, d=16, CAPS={8,7,6,5,4,3}, 5 routing iters
// ---------------------------------------------------------------------------

#define NNODES 20000
#define MNBR   16
#define FEAT   500
#define OUTW   656

// scratch (device global; no allocation allowed)
__device__ float g_xnorm[NNODES * 128];  // per-capsule L2-normalized x (compact KD)

// ---------------------------------------------------------------------------
// GEMM: val[M,N] = (relu?)(A[M,K] @ W[N,K]^T + bias[N])
//   epilogue: per-16-col-capsule L2 normalize -> xnorm (compact, row stride N)
//   WRITE_RAW: also store relu'd raw value to rawOut (PCA layer, jump connect)
// BM=128, BN=64, BKK=16, 256 threads, 8x4 per-thread microtile
// ---------------------------------------------------------------------------
#define BM 128
#define BN 64
#define BKK 16

template <bool WRITE_RAW>
__global__ void __launch_bounds__(256) gemm_norm_kernel(
    const float* __restrict__ A, int lda,
    const float* __restrict__ W, int ldw,
    const float* __restrict__ bias,
    float* __restrict__ rawOut, int ldo,
    float* __restrict__ xnorm,
    int Mdim, int Ndim, int Kdim)
{
    __shared__ float As[BKK][BM + 4];
    __shared__ float Ws[BKK][BN + 4];

    const int tid = threadIdx.x;
    const int tx = tid & 15;          // 0..15 -> 4 cols each
    const int ty = tid >> 4;          // 0..15 -> 8 rows each
    const int bm = blockIdx.y * BM;
    const int bn = blockIdx.x * BN;

    float acc[8][4];
#pragma unroll
    for (int i = 0; i < 8; ++i)
#pragma unroll
        for (int j = 0; j < 4; ++j) acc[i][j] = 0.f;

    for (int k0 = 0; k0 < Kdim; k0 += BKK) {
        const bool fullk = (k0 + BKK <= Kdim);
        // ---- load A tile: 512 float4, 2 per thread ----
#pragma unroll
        for (int l = 0; l < 2; ++l) {
            int idx = tid + l * 256;
            int r = idx >> 2;
            int c4 = (idx & 3) * 4;
            int gr = bm + r;
            if (fullk && gr < Mdim) {
                float4 v = *reinterpret_cast<const float4*>(A + (size_t)gr * lda + k0 + c4);
                As[c4 + 0][r] = v.x; As[c4 + 1][r] = v.y;
                As[c4 + 2][r] = v.z; As[c4 + 3][r] = v.w;
            } else {
#pragma unroll
                for (int q = 0; q < 4; ++q) {
                    int gc = k0 + c4 + q;
                    As[c4 + q][r] = (gr < Mdim && gc < Kdim)
                        ? A[(size_t)gr * lda + gc] : 0.f;
                }
            }
        }
        // ---- load W tile: 256 float4, 1 per thread ----
        {
            int r = tid >> 2;
            int c4 = (tid & 3) * 4;
            int gn = bn + r;
            if (fullk && gn < Ndim) {
                float4 v = *reinterpret_cast<const float4*>(W + (size_t)gn * ldw + k0 + c4);
                Ws[c4 + 0][r] = v.x; Ws[c4 + 1][r] = v.y;
                Ws[c4 + 2][r] = v.z; Ws[c4 + 3][r] = v.w;
            } else {
#pragma unroll
                for (int q = 0; q < 4; ++q) {
                    int gc = k0 + c4 + q;
                    Ws[c4 + q][r] = (gn < Ndim && gc < Kdim)
                        ? W[(size_t)gn * ldw + gc] : 0.f;
                }
            }
        }
        __syncthreads();

#pragma unroll
        for (int kk = 0; kk < BKK; ++kk) {
            float a[8], b[4];
#pragma unroll
            for (int i = 0; i < 8; ++i) a[i] = As[kk][ty * 8 + i];
#pragma unroll
            for (int j = 0; j < 4; ++j) b[j] = Ws[kk][tx * 4 + j];
#pragma unroll
            for (int i = 0; i < 8; ++i)
#pragma unroll
                for (int j = 0; j < 4; ++j) acc[i][j] += a[i] * b[j];
        }
        __syncthreads();
    }

    // ---- epilogue: bias (+relu) + per-capsule L2 normalize ----
    const int gc0 = bn + tx * 4;
    float bvals[4];
#pragma unroll
    for (int j = 0; j < 4; ++j) bvals[j] = (gc0 + j < Ndim) ? bias[gc0 + j] : 0.f;

#pragma unroll
    for (int i = 0; i < 8; ++i) {
        int gr = bm + ty * 8 + i;
        float v[4];
        float ssq = 0.f;
#pragma unroll
        for (int j = 0; j < 4; ++j) {
            float val = (gc0 + j < Ndim) ? acc[i][j] + bvals[j] : 0.f;
            if (WRITE_RAW) val = fmaxf(val, 0.f);
            v[j] = val;
            ssq += val * val;
        }
        // capsule (16 cols) spans 4 adjacent lanes (same ty, tx group of 4)
        ssq += __shfl_xor_sync(0xffffffffu, ssq, 1);
        ssq += __shfl_xor_sync(0xffffffffu, ssq, 2);
        float inv = 1.f / fmaxf(sqrtf(ssq), 1e-12f);
        if (gr < Mdim && gc0 < Ndim) {
            if (WRITE_RAW) {
                float4 o = make_float4(v[0], v[1], v[2], v[3]);
                *reinterpret_cast<float4*>(rawOut + (size_t)gr * ldo + gc0) = o;
            }
            float4 no = make_float4(v[0] * inv, v[1] * inv, v[2] * inv, v[3] * inv);
            *reinterpret_cast<float4*>(xnorm + (size_t)gr * Ndim + gc0) = no;
        }
    }
}

// ---------------------------------------------------------------------------
// Routing: one CTA per node, NT = 16*P threads (P = pow2 pad of K).
//  Phase A (scores): tid = m*P + k; z row cached in regs; softmax WITHOUT the
//    max-subtraction (scores are cosines in [-1,1], exp cannot overflow).
//    ps stored K-MAJOR: ps_t[k][m], row stride 20 floats (16B aligned, rows on
//    distinct banks; scatter write 20k+m conflict-free mod 32).
//  Phase B (agg): tid = q*2 + g; each thread owns 8 m's (z in regs);
//    ps column read = 2x LDS.128; reduce over g via shfl_xor 1; ssq xor 2,4.
// ---------------------------------------------------------------------------
template <int K>
__global__ void __launch_bounds__((K > 4) ? 128 : 64) routing_kernel(
    const float* __restrict__ xnorm,
    const int* __restrict__ nbid,
    float* __restrict__ outp)   // already offset to this layer's column block
{
    constexpr int P  = (K > 4) ? 8 : 4;    // padded capsule count (pow2)
    constexpr int NT = 16 * P;             // threads
    constexpr int KD = K * 16;
    constexpr int Q  = K * 4;              // float4 per node row
    constexpr int UP = 20;                 // u row stride (floats)
    constexpr int PST = 20;                // ps_t row stride (floats): 16 m + pad

    const int n = blockIdx.x;
    const int tid = threadIdx.x;

    __shared__ __align__(16) float z[16 * KD];
    __shared__ __align__(16) float u[8 * UP];
    __shared__ __align__(16) float ps[8 * PST];   // k-major: ps[k*PST + m]

    // init u = normalized self row (padded layout)
    if (tid < Q) {
        float4 v = reinterpret_cast<const float4*>(xnorm + (size_t)n * KD)[tid];
        *reinterpret_cast<float4*>(u + (tid >> 2) * UP + (tid & 3) * 4) = v;
    }

    // gather 16 neighbor rows into z (neighbor ids straight from L1/L2)
    {
        float4* z4 = reinterpret_cast<float4*>(z);
        for (int i = tid; i < 16 * Q; i += NT) {
            int j = i / Q;
            int w = i - j * Q;
            int nbj = __ldg(nbid + n * MNBR + j);
            z4[i] = reinterpret_cast<const float4*>(xnorm + (size_t)nbj * KD)[w];
        }
    }
    __syncthreads();

    // ---- phase-A mapping + reg cache: tid = mA*P + kA ----
    const int mA = tid / P;
    const int kA = tid & (P - 1);
    const bool validA = (kA < K);
    const int kAc = validA ? kA : (K - 1);
    float4 zp[4];
    {
        const float4* src = reinterpret_cast<const float4*>(z + mA * KD + kAc * 16);
        zp[0] = src[0]; zp[1] = src[1]; zp[2] = src[2]; zp[3] = src[3];
    }

    // ---- phase-B mapping + reg cache: tid = qB*2 + gB (8 m's per thread) ----
    const int qB = tid >> 1;
    const int gB = tid & 1;
    const bool validB = (tid < 2 * Q);
    const int qc = validB ? qB : (Q - 1);
    const int kB = qc >> 2;                // capsule of this q
    float4 za[8];
#pragma unroll
    for (int j = 0; j < 8; ++j)
        za[j] = reinterpret_cast<const float4*>(z)[(8 * gB + j) * Q + qc];
    // self slice for aggregation (added once, after g-reduction)
    float4 xs4 = *reinterpret_cast<const float4*>(u + kB * UP + (qc & 3) * 4);

#pragma unroll
    for (int t = 0; t < 5; ++t) {
        // ---- A: agreement p[m][k] = <z[m,k,:], u[k,:]> ----
        float p;
        {
            const float4* up = reinterpret_cast<const float4*>(u + kAc * UP);
            float pv = 0.f;
#pragma unroll
            for (int q = 0; q < 4; ++q) {
                float4 uu = up[q];
                pv += zp[q].x * uu.x + zp[q].y * uu.y + zp[q].z * uu.z + zp[q].w * uu.w;
            }
            p = validA ? pv : -1e30f;
        }
        // softmax over capsules (no max-sub: |p|<=1, padding exp -> 0)
        float e = __expf(p);
        float s = e;
        s += __shfl_xor_sync(0xffffffffu, s, 1);
        s += __shfl_xor_sync(0xffffffffu, s, 2);
        if (P == 8) s += __shfl_xor_sync(0xffffffffu, s, 4);
        float pr = __fdividef(e, s);
        if (validA) ps[kA * PST + mA] = pr;     // k-major scatter (conflict-free)
        __syncthreads();

        // ---- B: u[k][:] = xself + sum_m z[m][k][:] * p[m][k] ----
        float4 pa = *reinterpret_cast<const float4*>(ps + kB * PST + 8 * gB);
        float4 pb = *reinterpret_cast<const float4*>(ps + kB * PST + 8 * gB + 4);
        float pm[8] = {pa.x, pa.y, pa.z, pa.w, pb.x, pb.y, pb.z, pb.w};
        float4 acc = make_float4(0.f, 0.f, 0.f, 0.f);
#pragma unroll
        for (int j = 0; j < 8; ++j) {
            acc.x += za[j].x * pm[j]; acc.y += za[j].y * pm[j];
            acc.z += za[j].z * pm[j]; acc.w += za[j].w * pm[j];
        }
        // reduce over the 2 m-groups (adjacent lanes)
        acc.x += __shfl_xor_sync(0xffffffffu, acc.x, 1);
        acc.y += __shfl_xor_sync(0xffffffffu, acc.y, 1);
        acc.z += __shfl_xor_sync(0xffffffffu, acc.z, 1);
        acc.w += __shfl_xor_sync(0xffffffffu, acc.w, 1);
        acc.x += xs4.x; acc.y += xs4.y; acc.z += xs4.z; acc.w += xs4.w;

        if (t < 4) {
            // capsule L2: capsule spans 8 adjacent lanes (4 chunks x 2 dup)
            float sq = acc.x * acc.x + acc.y * acc.y + acc.z * acc.z + acc.w * acc.w;
            sq += __shfl_xor_sync(0xffffffffu, sq, 2);
            sq += __shfl_xor_sync(0xffffffffu, sq, 4);
            float inv = rsqrtf(fmaxf(sq, 1e-24f));
            if (validB && gB == 0) {
                float4 o = make_float4(acc.x * inv, acc.y * inv, acc.z * inv, acc.w * inv);
                *reinterpret_cast<float4*>(u + kB * UP + (qB & 3) * 4) = o;
            }
            __syncthreads();
        } else if (validB && gB == 0) {
            float4 o = make_float4(fmaxf(acc.x, 0.f), fmaxf(acc.y, 0.f),
                                   fmaxf(acc.z, 0.f), fmaxf(acc.w, 0.f));
            *reinterpret_cast<float4*>(outp + (size_t)n * OUTW + qB * 4) = o;
        }
    }
}

// ---------------------------------------------------------------------------
// host orchestration
// ---------------------------------------------------------------------------
extern "C" void kernel_launch(void* const* d_in, const int* in_sizes, int n_in,
                              void* d_out, int out_size)
{
    (void)in_sizes; (void)n_in; (void)out_size;
    const float* feature = (const float*)d_in[0];
    const int*   nbid    = (const int*)d_in[1];
    const float* pca_w   = (const float*)d_in[2];
    const float* pca_b   = (const float*)d_in[3];
    const float* W[6]  = {nullptr, (const float*)d_in[4], (const float*)d_in[6],
                          (const float*)d_in[8], (const float*)d_in[10], (const float*)d_in[12]};
    const float* Bb[6] = {nullptr, (const float*)d_in[5], (const float*)d_in[7],
                          (const float*)d_in[9], (const float*)d_in[11], (const float*)d_in[13]};
    float* out = (float*)d_out;

    static const int caps[6]   = {8, 7, 6, 5, 4, 3};
    static const int coloff[7] = {0, 128, 256, 368, 464, 544, 608};

    float* xnorm;
    cudaGetSymbolAddress((void**)&xnorm, g_xnorm);

    const int mblocks = (NNODES + BM - 1) / BM;   // 157

    // PCA: x0 = relu(feature @ pca_w.T + pca_b) -> out[:,0:128] + xnorm
    {
        dim3 grid((128 + BN - 1) / BN, mblocks);
        gemm_norm_kernel<true><<<grid, 256>>>(feature, FEAT, pca_w, FEAT, pca_b,
                                              out, OUTW, xnorm, NNODES, 128, FEAT);
    }

    for (int i = 0; i < 6; ++i) {
        int k = caps[i];
        int kd = k * 16;
        if (i > 0) {
            int fin = caps[i - 1] * 16;
            dim3 grid((kd + BN - 1) / BN, mblocks);
            gemm_norm_kernel<false><<<grid, 256>>>(out + coloff[i], OUTW,
                                                   W[i], fin, Bb[i],
                                                   nullptr, 0, xnorm,
                                                   NNODES, kd, fin);
        }
        float* dst = out + coloff[i + 1];
        switch (k) {
            case 8: routing_kernel<8><<<NNODES, 128>>>(xnorm, nbid, dst); break;
            case 7: routing_kernel<7><<<NNODES, 128>>>(xnorm, nbid, dst); break;
            case 6: routing_kernel<6><<<NNODES, 128>>>(xnorm, nbid, dst); break;
            case 5: routing_kernel<5><<<NNODES, 128>>>(xnorm, nbid, dst); break;
            case 4: routing_kernel<4><<<NNODES, 64>>>(xnorm, nbid, dst); break;
            case 3: routing_kernel<3><<<NNODES, 64>>>(xnorm, nbid, dst); break;
        }
    }
}